// round 15
// baseline (speedup 1.0000x reference)
#include <cuda_runtime.h>
#include <cuda_fp16.h>
#include <math.h>

#define N_NODES 100000
#define N_EDGES 1600000
#define H 64
#define SCAN_T 1024
#define SCAN_B ((N_NODES + SCAN_T - 1) / SCAN_T)   // 98
#define FILL_BLOCKS 3125                            // N_EDGES/2 / 256
#define GEMM_BLOCKS 391                             // ceil(N_NODES/256)

// Scratch (device globals — no allocation allowed)
__device__ int    g_degi[N_NODES];
__device__ float  g_dinv[N_NODES];
__device__ int    g_rowptr[N_NODES];       // exclusive-within-block partials
__device__ int    g_bsum[SCAN_B];
__device__ int    g_boff[SCAN_B];          // exclusive block offsets
__device__ int    g_rank[N_EDGES];         // edge rank within its dst row
__device__ int    g_ticket;
__device__ int    g_esrc[N_EDGES];         // CSR: src index only (norm factored out)
__device__ __half g_yh0[(size_t)N_NODES * H];  // y' ping
__device__ __half g_yh1[(size_t)N_NODES * H];  // y' pong

__global__ void zero_kernel() {
    int i = blockIdx.x * blockDim.x + threadIdx.x;
    if (i < N_NODES) g_degi[i] = 0;
    if (i == 0) g_ticket = 0;
}

// Histogram over dst (2 edges/thread, int2); old count = edge's rank in its row.
__global__ void hist_kernel(const int* __restrict__ ei) {
    int i = blockIdx.x * blockDim.x + threadIdx.x;
    int e = 2 * i;
    if (e + 1 < N_EDGES) {
        int2 d = *(const int2*)&ei[N_EDGES + e];
        int r0 = atomicAdd(&g_degi[d.x], 1);
        int r1 = atomicAdd(&g_degi[d.y], 1);
        *(int2*)&g_rank[e] = make_int2(r0, r1);
    }
}

// Per-block scan of degrees (+ fused dinv). Last block to finish also scans
// the 98 block sums into g_boff (decoupled via ticket + threadfence).
__global__ void __launch_bounds__(SCAN_T) scanA_kernel() {
    __shared__ int s[SCAN_T];
    __shared__ int s2[128];
    __shared__ int isLast;
    int t = threadIdx.x;
    int i = blockIdx.x * SCAN_T + t;
    int v = (i < N_NODES) ? g_degi[i] : 0;
    if (i < N_NODES) g_dinv[i] = rsqrtf((float)(v + 1));
    s[t] = v;
    __syncthreads();
    for (int off = 1; off < SCAN_T; off <<= 1) {
        int tmp = 0;
        if (t >= off) tmp = s[t - off];
        __syncthreads();
        if (t >= off) s[t] += tmp;
        __syncthreads();
    }
    if (i < N_NODES) g_rowptr[i] = s[t] - v;  // exclusive within block
    if (t == SCAN_T - 1) g_bsum[blockIdx.x] = s[t];

    if (t == 0) {
        __threadfence();
        int prev = atomicAdd(&g_ticket, 1);
        isLast = (prev == gridDim.x - 1) ? 1 : 0;
    }
    __syncthreads();
    if (!isLast) return;
    __threadfence();  // acquire bsum writes

    int v2 = (t < SCAN_B) ? g_bsum[t] : 0;
    if (t < 128) s2[t] = v2;
    __syncthreads();
    for (int off = 1; off < 128; off <<= 1) {
        int tmp = 0;
        if (t >= off && t < 128) tmp = s2[t - off];
        __syncthreads();
        if (t >= off && t < 128) s2[t] += tmp;
        __syncthreads();
    }
    if (t < SCAN_B) g_boff[t] = s2[t] - v2;  // exclusive
}

// Fused: blocks [0,FILL_BLOCKS) do CSR fill (L2-bound); blocks
// [FILL_BLOCKS, FILL_BLOCKS+GEMM_BLOCKS) do the layer-1 GEMM (tensor-bound).
// GEMM: y0' = (emb @ W1) * dinv[row], fp16 out, fp32 accumulate.
__global__ void __launch_bounds__(256, 2) fillgemm_kernel(
    const int* __restrict__ ei, const float* __restrict__ x_ext,
    const float* __restrict__ W)
{
    __shared__ __half Wt[64][72];   // only used by gemm blocks

    if (blockIdx.x < FILL_BLOCKS) {
        int i = blockIdx.x * 256 + threadIdx.x;
        int e = 2 * i;
        if (e + 1 < N_EDGES) {
            int2 sv = *(const int2*)&ei[e];
            int2 dv = *(const int2*)&ei[N_EDGES + e];
            int2 rv = *(const int2*)&g_rank[e];
            g_esrc[g_rowptr[dv.x] + g_boff[dv.x >> 10] + rv.x] = sv.x;
            g_esrc[g_rowptr[dv.y] + g_boff[dv.y >> 10] + rv.y] = sv.y;
        }
        return;
    }

    // ---- GEMM blocks ----
    const int tid = threadIdx.x;
    for (int i = tid; i < 64 * 64; i += 256) {
        int k = i >> 6, c = i & 63;
        Wt[c][k] = __float2half(W[i]);
    }
    __syncthreads();

    const int w = tid >> 5;          // 8 warps, 32 rows each
    const int lane = tid & 31;
    const int qr = lane >> 2;
    const int qc = (lane & 3) * 2;
    const int r0 = (blockIdx.x - FILL_BLOCKS) * 256 + w * 32;

    int rowa[2], rowb[2];
#pragma unroll
    for (int t = 0; t < 2; t++) {
        int ra = r0 + t * 16 + qr;
        int rb = ra + 8;
        rowa[t] = (ra < N_NODES) ? ra : N_NODES - 1;
        rowb[t] = (rb < N_NODES) ? rb : N_NODES - 1;
    }

    float acc[2][8][4];
#pragma unroll
    for (int t = 0; t < 2; t++)
#pragma unroll
        for (int n = 0; n < 8; n++)
#pragma unroll
            for (int i = 0; i < 4; i++) acc[t][n][i] = 0.f;

#pragma unroll
    for (int ks = 0; ks < 4; ks++) {
        int k0 = ks * 16;
        unsigned a[2][4];
#pragma unroll
        for (int t = 0; t < 2; t++) {
            float2 v0 = *(const float2*)&x_ext[(size_t)rowa[t] * H + k0 + qc];
            float2 v1 = *(const float2*)&x_ext[(size_t)rowb[t] * H + k0 + qc];
            float2 v2 = *(const float2*)&x_ext[(size_t)rowa[t] * H + k0 + qc + 8];
            float2 v3 = *(const float2*)&x_ext[(size_t)rowb[t] * H + k0 + qc + 8];
            __half2 h0 = __floats2half2_rn(v0.x, v0.y);
            __half2 h1 = __floats2half2_rn(v1.x, v1.y);
            __half2 h2 = __floats2half2_rn(v2.x, v2.y);
            __half2 h3 = __floats2half2_rn(v3.x, v3.y);
            a[t][0] = *(unsigned*)&h0;
            a[t][1] = *(unsigned*)&h1;
            a[t][2] = *(unsigned*)&h2;
            a[t][3] = *(unsigned*)&h3;
        }
#pragma unroll
        for (int n = 0; n < 8; n++) {
            unsigned b0 = *(const unsigned*)&Wt[n * 8 + qr][k0 + qc];
            unsigned b1 = *(const unsigned*)&Wt[n * 8 + qr][k0 + qc + 8];
#pragma unroll
            for (int t = 0; t < 2; t++) {
                asm("mma.sync.aligned.m16n8k16.row.col.f32.f16.f16.f32 "
                    "{%0,%1,%2,%3}, {%4,%5,%6,%7}, {%8,%9}, {%0,%1,%2,%3};"
                    : "+f"(acc[t][n][0]), "+f"(acc[t][n][1]),
                      "+f"(acc[t][n][2]), "+f"(acc[t][n][3])
                    : "r"(a[t][0]), "r"(a[t][1]), "r"(a[t][2]), "r"(a[t][3]),
                      "r"(b0), "r"(b1));
            }
        }
    }

#pragma unroll
    for (int t = 0; t < 2; t++) {
        int row0 = r0 + t * 16 + qr;
        int row1 = row0 + 8;
        float d0 = (row0 < N_NODES) ? g_dinv[row0] : 0.f;
        float d1 = (row1 < N_NODES) ? g_dinv[row1] : 0.f;
#pragma unroll
        for (int n = 0; n < 8; n++) {
            int col = n * 8 + qc;
            if (row0 < N_NODES)
                *(__half2*)&g_yh0[(size_t)row0 * H + col] =
                    __floats2half2_rn(acc[t][n][0] * d0, acc[t][n][1] * d0);
            if (row1 < N_NODES)
                *(__half2*)&g_yh0[(size_t)row1 * H + col] =
                    __floats2half2_rn(acc[t][n][2] * d1, acc[t][n][3] * d1);
        }
    }
}

// Pull + fused next-layer MMA epilogue.
// Block: 512 threads = 16 warps = 16 dsts (N_NODES = 6250*16 exact).
// Main: t[w] = dinv[dst]*( sum_e y'in[src] + y'in[dst] ) + bias   (fp32)
// mode==1: stage t rows as fp16 in smem; 4 warps compute (t @ Wnext)*dinv
//          with mma.sync and write y'out (ping-pong buffer).
// mode==0: write t to out_ext (fp32 final).
// ysel: 0 = read g_yh0/write g_yh1 ; 1 = read g_yh1/write g_yh0
__global__ void __launch_bounds__(512, 2) pull_kernel(
    const float* __restrict__ bias, const float* __restrict__ Wnext,
    float* __restrict__ out_ext, int ysel, int mode)
{
    __shared__ __half Wt[64][72];
    __shared__ __half tb[16][72];

    const __half* yin  = ysel ? g_yh1 : g_yh0;
    __half*       yout = ysel ? g_yh0 : g_yh1;

    const int tid = threadIdx.x;
    const int w = tid >> 5;
    const int lane = tid & 31;
    const int q = lane & 7;
    const int h = lane >> 3;
    const int dstBase = blockIdx.x * 16;
    const int dst = dstBase + w;

    if (mode) {
        for (int i = tid; i < 64 * 64; i += 512) {
            int k = i >> 6, c = i & 63;
            Wt[c][k] = __float2half(Wnext[i]);
        }
        __syncthreads();
    }

    int beg = g_rowptr[dst] + g_boff[dst >> 10];
    int end = (dst + 1 < N_NODES) ? (g_rowptr[dst + 1] + g_boff[(dst + 1) >> 10])
                                  : N_EDGES;

    const uint4* y16 = (const uint4*)yin;  // 8 uint4 per row

    float4 a0 = make_float4(0.f, 0.f, 0.f, 0.f);
    float4 a1 = make_float4(0.f, 0.f, 0.f, 0.f);

#pragma unroll 2
    for (int j = beg + h; j < end; j += 4) {
        int src = __ldg(&g_esrc[j]);
        uint4 v = y16[(size_t)src * 8 + q];
        const __half2* hp = (const __half2*)&v;
        float2 f0 = __half22float2(hp[0]);
        float2 f1 = __half22float2(hp[1]);
        float2 f2 = __half22float2(hp[2]);
        float2 f3 = __half22float2(hp[3]);
        a0.x += f0.x; a0.y += f0.y;
        a0.z += f1.x; a0.w += f1.y;
        a1.x += f2.x; a1.y += f2.y;
        a1.z += f3.x; a1.w += f3.y;
    }

#pragma unroll
    for (int off = 8; off < 32; off <<= 1) {
        a0.x += __shfl_xor_sync(0xFFFFFFFFu, a0.x, off);
        a0.y += __shfl_xor_sync(0xFFFFFFFFu, a0.y, off);
        a0.z += __shfl_xor_sync(0xFFFFFFFFu, a0.z, off);
        a0.w += __shfl_xor_sync(0xFFFFFFFFu, a0.w, off);
        a1.x += __shfl_xor_sync(0xFFFFFFFFu, a1.x, off);
        a1.y += __shfl_xor_sync(0xFFFFFFFFu, a1.y, off);
        a1.z += __shfl_xor_sync(0xFFFFFFFFu, a1.z, off);
        a1.w += __shfl_xor_sync(0xFFFFFFFFu, a1.w, off);
    }

    if (h == 0) {
        float di = g_dinv[dst];
        uint4 v = y16[(size_t)dst * 8 + q];
        const __half2* hp = (const __half2*)&v;
        float2 f0 = __half22float2(hp[0]);
        float2 f1 = __half22float2(hp[1]);
        float2 f2 = __half22float2(hp[2]);
        float2 f3 = __half22float2(hp[3]);
        float4 bv0 = ((const float4*)bias)[q * 2];
        float4 bv1 = ((const float4*)bias)[q * 2 + 1];
        float4 t0, t1;
        t0.x = fmaf(a0.x + f0.x, di, bv0.x);
        t0.y = fmaf(a0.y + f0.y, di, bv0.y);
        t0.z = fmaf(a0.z + f1.x, di, bv0.z);
        t0.w = fmaf(a0.w + f1.y, di, bv0.w);
        t1.x = fmaf(a1.x + f2.x, di, bv1.x);
        t1.y = fmaf(a1.y + f2.y, di, bv1.y);
        t1.z = fmaf(a1.z + f3.x, di, bv1.z);
        t1.w = fmaf(a1.w + f3.y, di, bv1.w);
        if (mode) {
            uint4 o;
            __half2 h0 = __floats2half2_rn(t0.x, t0.y);
            __half2 h1 = __floats2half2_rn(t0.z, t0.w);
            __half2 h2 = __floats2half2_rn(t1.x, t1.y);
            __half2 h3 = __floats2half2_rn(t1.z, t1.w);
            o.x = *(unsigned*)&h0; o.y = *(unsigned*)&h1;
            o.z = *(unsigned*)&h2; o.w = *(unsigned*)&h3;
            *(uint4*)&tb[w][q * 8] = o;
        } else {
            float4* orow = (float4*)out_ext + (size_t)dst * 16;
            orow[q * 2]     = t0;
            orow[q * 2 + 1] = t1;
        }
    }

    if (mode) {
        __syncthreads();
        if (w < 4) {
            // Epilogue: C[16][64] = tb @ Wnext; warp w covers n-tiles {2w, 2w+1}.
            const int qr = lane >> 2;
            const int qc2 = (lane & 3) * 2;

            unsigned a[4][4];
#pragma unroll
            for (int ks = 0; ks < 4; ks++) {
                int k0 = ks * 16;
                a[ks][0] = *(const unsigned*)&tb[qr][k0 + qc2];
                a[ks][1] = *(const unsigned*)&tb[qr + 8][k0 + qc2];
                a[ks][2] = *(const unsigned*)&tb[qr][k0 + qc2 + 8];
                a[ks][3] = *(const unsigned*)&tb[qr + 8][k0 + qc2 + 8];
            }

            float acc[2][4];
#pragma unroll
            for (int nt = 0; nt < 2; nt++)
#pragma unroll
                for (int i = 0; i < 4; i++) acc[nt][i] = 0.f;

#pragma unroll
            for (int ks = 0; ks < 4; ks++) {
                int k0 = ks * 16;
#pragma unroll
                for (int nt = 0; nt < 2; nt++) {
                    int n = w * 2 + nt;
                    unsigned b0 = *(const unsigned*)&Wt[n * 8 + qr][k0 + qc2];
                    unsigned b1 = *(const unsigned*)&Wt[n * 8 + qr][k0 + qc2 + 8];
                    asm("mma.sync.aligned.m16n8k16.row.col.f32.f16.f16.f32 "
                        "{%0,%1,%2,%3}, {%4,%5,%6,%7}, {%8,%9}, {%0,%1,%2,%3};"
                        : "+f"(acc[nt][0]), "+f"(acc[nt][1]),
                          "+f"(acc[nt][2]), "+f"(acc[nt][3])
                        : "r"(a[ks][0]), "r"(a[ks][1]), "r"(a[ks][2]), "r"(a[ks][3]),
                          "r"(b0), "r"(b1));
                }
            }

            int dst0 = dstBase + qr;
            int dst1 = dst0 + 8;
            float d0 = g_dinv[dst0];
            float d1 = g_dinv[dst1];
#pragma unroll
            for (int nt = 0; nt < 2; nt++) {
                int col = (w * 2 + nt) * 8 + qc2;
                *(__half2*)&yout[(size_t)dst0 * H + col] =
                    __floats2half2_rn(acc[nt][0] * d0, acc[nt][1] * d0);
                *(__half2*)&yout[(size_t)dst1 * H + col] =
                    __floats2half2_rn(acc[nt][2] * d1, acc[nt][3] * d1);
            }
        }
    }
}

extern "C" void kernel_launch(void* const* d_in, const int* in_sizes, int n_in,
                              void* d_out, int out_size)
{
    const float* emb = (const float*)d_in[0];
    const int*   ei  = (const int*)d_in[1];
    const float* W1  = (const float*)d_in[2];
    const float* b1  = (const float*)d_in[3];
    const float* W2  = (const float*)d_in[4];
    const float* b2  = (const float*)d_in[5];
    const float* W3  = (const float*)d_in[6];
    const float* b3  = (const float*)d_in[7];
    float* out = (float*)d_out;

    const int node_blocks = (N_NODES + 255) / 256;
    const int edge2_blocks = (N_EDGES / 2 + 255) / 256;   // 3125
    const int pull_blocks = N_NODES / 16;                 // 6250, exact

    // ---- CSR build (fill fused with layer-1 GEMM) ----
    zero_kernel<<<node_blocks, 256>>>();
    hist_kernel<<<edge2_blocks, 256>>>(ei);
    scanA_kernel<<<SCAN_B, SCAN_T>>>();
    fillgemm_kernel<<<FILL_BLOCKS + GEMM_BLOCKS, 256>>>(ei, emb, W1);

    // ---- Pull 1 (+ W2 epilogue): yh0 -> yh1 ----
    pull_kernel<<<pull_blocks, 512>>>(b1, W2, out, /*ysel=*/0, /*mode=*/1);
    // ---- Pull 2 (+ W3 epilogue): yh1 -> yh0 ----
    pull_kernel<<<pull_blocks, 512>>>(b2, W3, out, /*ysel=*/1, /*mode=*/1);
    // ---- Pull 3 (final): yh0 -> d_out fp32 ----
    pull_kernel<<<pull_blocks, 512>>>(b3, W3, out, /*ysel=*/0, /*mode=*/0);
}

// round 16
// speedup vs baseline: 1.2375x; 1.2375x over previous
#include <cuda_runtime.h>
#include <cuda_fp16.h>
#include <math.h>

#define N_NODES 100000
#define N_EDGES 1600000
#define H 64
#define SCAN_T 1024
#define SCAN_B ((N_NODES + SCAN_T - 1) / SCAN_T)   // 98

// Scratch (device globals — no allocation allowed).
// INVARIANT: g_degi and g_ticket are all-zero at kernel_launch entry and are
// restored to zero by scanA_kernel within the same launch (replay-safe).
__device__ int    g_degi[N_NODES];
__device__ float  g_dinv[N_NODES];
__device__ int    g_rowptr[N_NODES];       // exclusive-within-block partials
__device__ int    g_bsum[SCAN_B];
__device__ int    g_boff[SCAN_B];          // exclusive block offsets
__device__ int    g_rank[N_EDGES];         // edge rank within its dst row
__device__ int    g_ticket;
__device__ int    g_esrc[N_EDGES];         // CSR: src index only (norm factored out)
__device__ __half g_yh[(size_t)N_NODES * H];   // y' = (xW)*dinv (fp16, gather target)
__device__ __half g_xh[(size_t)N_NODES * H];   // intermediate layer output (fp16)

// Histogram over dst (2 edges/thread, int2); old count = edge's rank in its row.
__global__ void hist_kernel(const int* __restrict__ ei) {
    int i = blockIdx.x * blockDim.x + threadIdx.x;
    int e = 2 * i;
    if (e + 1 < N_EDGES) {
        int2 d = *(const int2*)&ei[N_EDGES + e];
        int r0 = atomicAdd(&g_degi[d.x], 1);
        int r1 = atomicAdd(&g_degi[d.y], 1);
        *(int2*)&g_rank[e] = make_int2(r0, r1);
    }
}

// Per-block scan of degrees (+ fused dinv). Resets g_degi to zero in-place
// (restores the launch invariant). Last block to finish also scans the 98
// block sums into g_boff (decoupled via ticket + threadfence) and resets
// the ticket.
__global__ void __launch_bounds__(SCAN_T) scanA_kernel() {
    __shared__ int s[SCAN_T];
    __shared__ int s2[128];
    __shared__ int isLast;
    int t = threadIdx.x;
    int i = blockIdx.x * SCAN_T + t;
    int v = (i < N_NODES) ? g_degi[i] : 0;
    if (i < N_NODES) {
        g_dinv[i] = rsqrtf((float)(v + 1));
        g_degi[i] = 0;                      // restore invariant for next launch
    }
    s[t] = v;
    __syncthreads();
    for (int off = 1; off < SCAN_T; off <<= 1) {
        int tmp = 0;
        if (t >= off) tmp = s[t - off];
        __syncthreads();
        if (t >= off) s[t] += tmp;
        __syncthreads();
    }
    if (i < N_NODES) g_rowptr[i] = s[t] - v;  // exclusive within block
    if (t == SCAN_T - 1) g_bsum[blockIdx.x] = s[t];

    if (t == 0) {
        __threadfence();
        int prev = atomicAdd(&g_ticket, 1);
        isLast = (prev == gridDim.x - 1) ? 1 : 0;
    }
    __syncthreads();
    if (!isLast) return;
    __threadfence();  // acquire bsum writes

    if (t == 0) g_ticket = 0;               // restore invariant

    int v2 = (t < SCAN_B) ? g_bsum[t] : 0;
    if (t < 128) s2[t] = v2;
    __syncthreads();
    for (int off = 1; off < 128; off <<= 1) {
        int tmp = 0;
        if (t >= off && t < 128) tmp = s2[t - off];
        __syncthreads();
        if (t >= off && t < 128) s2[t] += tmp;
        __syncthreads();
    }
    if (t < SCAN_B) g_boff[t] = s2[t] - v2;  // exclusive
}

// CSR fill: pure permutation of src indices, 2 edges/thread.
__global__ void fill_kernel(const int* __restrict__ ei) {
    int i = blockIdx.x * blockDim.x + threadIdx.x;
    int e = 2 * i;
    if (e + 1 < N_EDGES) {
        int2 sv = *(const int2*)&ei[e];
        int2 dv = *(const int2*)&ei[N_EDGES + e];
        int2 rv = *(const int2*)&g_rank[e];
        g_esrc[g_rowptr[dv.x] + g_boff[dv.x >> 10] + rv.x] = sv.x;
        g_esrc[g_rowptr[dv.y] + g_boff[dv.y >> 10] + rv.y] = sv.y;
    }
}

// Tensor-core GEMM: y' = (x @ W) * dinv[row]  (fp16 out, fp32 accumulate).
// 128 threads = 4 warps = 128 rows/block. A fragments loaded DIRECTLY from
// global; only Wt staged in smem. No barrier in the hot path.
// xsel: 0 = fp32 embeddings (convert in flight), 1 = fp16 g_xh.
__global__ void __launch_bounds__(128, 4) gemm_kernel(
    const float* __restrict__ x_ext, const float* __restrict__ W, int xsel)
{
    __shared__ __half Wt[64][72];    // 9216 B : Wt[c][k] = W[k][c]

    const int tid = threadIdx.x;
    for (int i = tid; i < 64 * 64; i += 128) {
        int k = i >> 6, c = i & 63;
        Wt[c][k] = __float2half(W[i]);
    }
    __syncthreads();

    const int w = tid >> 5;
    const int lane = tid & 31;
    const int qr = lane >> 2;        // group row 0..7
    const int qc = (lane & 3) * 2;   // k-pair col 0,2,4,6
    const int r0 = blockIdx.x * 128 + w * 32;

    int rowa[2], rowb[2];
#pragma unroll
    for (int t = 0; t < 2; t++) {
        int ra = r0 + t * 16 + qr;
        int rb = ra + 8;
        rowa[t] = (ra < N_NODES) ? ra : N_NODES - 1;
        rowb[t] = (rb < N_NODES) ? rb : N_NODES - 1;
    }

    float acc[2][8][4];
#pragma unroll
    for (int t = 0; t < 2; t++)
#pragma unroll
        for (int n = 0; n < 8; n++)
#pragma unroll
            for (int i = 0; i < 4; i++) acc[t][n][i] = 0.f;

#pragma unroll
    for (int ks = 0; ks < 4; ks++) {
        int k0 = ks * 16;
        unsigned a[2][4];
        if (xsel == 0) {
#pragma unroll
            for (int t = 0; t < 2; t++) {
                float2 v0 = *(const float2*)&x_ext[(size_t)rowa[t] * H + k0 + qc];
                float2 v1 = *(const float2*)&x_ext[(size_t)rowb[t] * H + k0 + qc];
                float2 v2 = *(const float2*)&x_ext[(size_t)rowa[t] * H + k0 + qc + 8];
                float2 v3 = *(const float2*)&x_ext[(size_t)rowb[t] * H + k0 + qc + 8];
                __half2 h0 = __floats2half2_rn(v0.x, v0.y);
                __half2 h1 = __floats2half2_rn(v1.x, v1.y);
                __half2 h2 = __floats2half2_rn(v2.x, v2.y);
                __half2 h3 = __floats2half2_rn(v3.x, v3.y);
                a[t][0] = *(unsigned*)&h0;
                a[t][1] = *(unsigned*)&h1;
                a[t][2] = *(unsigned*)&h2;
                a[t][3] = *(unsigned*)&h3;
            }
        } else {
#pragma unroll
            for (int t = 0; t < 2; t++) {
                a[t][0] = *(const unsigned*)&g_xh[(size_t)rowa[t] * H + k0 + qc];
                a[t][1] = *(const unsigned*)&g_xh[(size_t)rowb[t] * H + k0 + qc];
                a[t][2] = *(const unsigned*)&g_xh[(size_t)rowa[t] * H + k0 + qc + 8];
                a[t][3] = *(const unsigned*)&g_xh[(size_t)rowb[t] * H + k0 + qc + 8];
            }
        }
#pragma unroll
        for (int n = 0; n < 8; n++) {
            unsigned b0 = *(const unsigned*)&Wt[n * 8 + qr][k0 + qc];
            unsigned b1 = *(const unsigned*)&Wt[n * 8 + qr][k0 + qc + 8];
#pragma unroll
            for (int t = 0; t < 2; t++) {
                asm("mma.sync.aligned.m16n8k16.row.col.f32.f16.f16.f32 "
                    "{%0,%1,%2,%3}, {%4,%5,%6,%7}, {%8,%9}, {%0,%1,%2,%3};"
                    : "+f"(acc[t][n][0]), "+f"(acc[t][n][1]),
                      "+f"(acc[t][n][2]), "+f"(acc[t][n][3])
                    : "r"(a[t][0]), "r"(a[t][1]), "r"(a[t][2]), "r"(a[t][3]),
                      "r"(b0), "r"(b1));
            }
        }
    }

    // Write y' = y * dinv (fp16). c0,c1 -> row qr; c2,c3 -> row qr+8.
#pragma unroll
    for (int t = 0; t < 2; t++) {
        int row0 = r0 + t * 16 + qr;
        int row1 = row0 + 8;
        float d0 = (row0 < N_NODES) ? g_dinv[row0] : 0.f;
        float d1 = (row1 < N_NODES) ? g_dinv[row1] : 0.f;
#pragma unroll
        for (int n = 0; n < 8; n++) {
            int col = n * 8 + qc;
            if (row0 < N_NODES)
                *(__half2*)&g_yh[(size_t)row0 * H + col] =
                    __floats2half2_rn(acc[t][n][0] * d0, acc[t][n][1] * d0);
            if (row1 < N_NODES)
                *(__half2*)&g_yh[(size_t)row1 * H + col] =
                    __floats2half2_rn(acc[t][n][2] * d1, acc[t][n][3] * d1);
        }
    }
}

// Pull: one warp per dst. q = lane&7 (16B = 8 fp16 cols), h = lane>>3 (4 edge slots).
// t = dinv[dst] * ( sum_e y'[src_e] + y'[dst] ) + b   (fp32 accumulate)
// mode==1: g_xh[dst] = t (fp16) ; mode==0: out[dst] = t (fp32, final)
__global__ void __launch_bounds__(256) pull_kernel(
    const float* __restrict__ bias, float* __restrict__ out_ext, int mode)
{
    int warp = (blockIdx.x * 256 + threadIdx.x) >> 5;   // grid exact: N_NODES warps
    int dst = warp;
    int lane = threadIdx.x & 31;
    int q = lane & 7;
    int h = lane >> 3;

    int beg = g_rowptr[dst] + g_boff[dst >> 10];
    int end = (dst + 1 < N_NODES) ? (g_rowptr[dst + 1] + g_boff[(dst + 1) >> 10])
                                  : N_EDGES;

    const uint4* y16 = (const uint4*)g_yh;  // 8 uint4 per row

    float4 a0 = make_float4(0.f, 0.f, 0.f, 0.f);
    float4 a1 = make_float4(0.f, 0.f, 0.f, 0.f);

#pragma unroll 2
    for (int j = beg + h; j < end; j += 4) {
        int src = __ldg(&g_esrc[j]);
        uint4 v = y16[(size_t)src * 8 + q];
        const __half2* hp = (const __half2*)&v;
        float2 f0 = __half22float2(hp[0]);
        float2 f1 = __half22float2(hp[1]);
        float2 f2 = __half22float2(hp[2]);
        float2 f3 = __half22float2(hp[3]);
        a0.x += f0.x; a0.y += f0.y;
        a0.z += f1.x; a0.w += f1.y;
        a1.x += f2.x; a1.y += f2.y;
        a1.z += f3.x; a1.w += f3.y;
    }

#pragma unroll
    for (int off = 8; off < 32; off <<= 1) {
        a0.x += __shfl_xor_sync(0xFFFFFFFFu, a0.x, off);
        a0.y += __shfl_xor_sync(0xFFFFFFFFu, a0.y, off);
        a0.z += __shfl_xor_sync(0xFFFFFFFFu, a0.z, off);
        a0.w += __shfl_xor_sync(0xFFFFFFFFu, a0.w, off);
        a1.x += __shfl_xor_sync(0xFFFFFFFFu, a1.x, off);
        a1.y += __shfl_xor_sync(0xFFFFFFFFu, a1.y, off);
        a1.z += __shfl_xor_sync(0xFFFFFFFFu, a1.z, off);
        a1.w += __shfl_xor_sync(0xFFFFFFFFu, a1.w, off);
    }

    if (h == 0) {
        float di = g_dinv[dst];
        uint4 v = y16[(size_t)dst * 8 + q];
        const __half2* hp = (const __half2*)&v;
        float2 f0 = __half22float2(hp[0]);
        float2 f1 = __half22float2(hp[1]);
        float2 f2 = __half22float2(hp[2]);
        float2 f3 = __half22float2(hp[3]);
        float4 bv0 = ((const float4*)bias)[q * 2];
        float4 bv1 = ((const float4*)bias)[q * 2 + 1];
        float4 t0, t1;
        t0.x = fmaf(a0.x + f0.x, di, bv0.x);
        t0.y = fmaf(a0.y + f0.y, di, bv0.y);
        t0.z = fmaf(a0.z + f1.x, di, bv0.z);
        t0.w = fmaf(a0.w + f1.y, di, bv0.w);
        t1.x = fmaf(a1.x + f2.x, di, bv1.x);
        t1.y = fmaf(a1.y + f2.y, di, bv1.y);
        t1.z = fmaf(a1.z + f3.x, di, bv1.z);
        t1.w = fmaf(a1.w + f3.y, di, bv1.w);
        if (mode) {
            uint4 o;
            __half2 h0 = __floats2half2_rn(t0.x, t0.y);
            __half2 h1 = __floats2half2_rn(t0.z, t0.w);
            __half2 h2 = __floats2half2_rn(t1.x, t1.y);
            __half2 h3 = __floats2half2_rn(t1.z, t1.w);
            o.x = *(unsigned*)&h0; o.y = *(unsigned*)&h1;
            o.z = *(unsigned*)&h2; o.w = *(unsigned*)&h3;
            ((uint4*)g_xh)[(size_t)dst * 8 + q] = o;
        } else {
            float4* orow = (float4*)out_ext + (size_t)dst * 16;
            orow[q * 2]     = t0;
            orow[q * 2 + 1] = t1;
        }
    }
}

extern "C" void kernel_launch(void* const* d_in, const int* in_sizes, int n_in,
                              void* d_out, int out_size)
{
    const float* emb = (const float*)d_in[0];
    const int*   ei  = (const int*)d_in[1];
    const float* W1  = (const float*)d_in[2];
    const float* b1  = (const float*)d_in[3];
    const float* W2  = (const float*)d_in[4];
    const float* b2  = (const float*)d_in[5];
    const float* W3  = (const float*)d_in[6];
    const float* b3  = (const float*)d_in[7];
    float* out = (float*)d_out;

    const int edge2_blocks = (N_EDGES / 2 + 255) / 256;   // 3125
    const int gemm_blocks = (N_NODES + 127) / 128;        // 782
    const int pull_blocks = N_NODES / 8;                  // 12500, exact

    // ---- CSR build (g_degi/g_ticket self-reset inside scanA) ----
    hist_kernel<<<edge2_blocks, 256>>>(ei);
    scanA_kernel<<<SCAN_B, SCAN_T>>>();
    fill_kernel<<<edge2_blocks, 256>>>(ei);

    // ---- Layer 1: emb -> g_xh ----
    gemm_kernel<<<gemm_blocks, 128>>>(emb, W1, /*xsel=*/0);
    pull_kernel<<<pull_blocks, 256>>>(b1, out, /*mode=*/1);

    // ---- Layer 2: g_xh -> g_xh ----
    gemm_kernel<<<gemm_blocks, 128>>>(emb, W2, /*xsel=*/1);
    pull_kernel<<<pull_blocks, 256>>>(b2, out, /*mode=*/1);

    // ---- Layer 3: g_xh -> d_out (fp32) ----
    gemm_kernel<<<gemm_blocks, 128>>>(emb, W3, /*xsel=*/1);
    pull_kernel<<<pull_blocks, 256>>>(b3, out, /*mode=*/0);
}